// round 11
// baseline (speedup 1.0000x reference)
#include <cuda_runtime.h>
#include <cuda_bf16.h>
#include <cstdint>
#include <math.h>

#define TOKENS 16384
#define D_IN   2048
#define D_HID  1024
#define N_EXP  64
#define TOPK   8
#define SLOPE  0.01f
#define KSPLIT1 512   // GEMM1: 4 panels of 512, sequential folds
#define KSPLIT2 256   // GEMM2: 4 panels of 256, pairwise-tree fold

// Scratch for hidden activations H [TOKENS, D_HID] (64 MB)
__device__ float g_H[(size_t)TOKENS * D_HID];

// ---------------------------------------------------------------------------
// GEMM1: H = leaky_relu(X @ W1^T + b1)
// Ordering draw: 4 panels of 512; ascending FMA chain within a panel;
// panels folded sequentially ((((p0)+p1)+p2)+p3).
// 128x128 tile, BK=16, 256 threads, 8x8 microtile.
// ---------------------------------------------------------------------------
#define BM 128
#define BN 128
#define BK 16
#define TM 8
#define TN 8

__global__ __launch_bounds__(256)
void gemm1_kernel(const float* __restrict__ X,
                  const float* __restrict__ W1,
                  const float* __restrict__ b1)
{
    __shared__ float As[BK][BM];
    __shared__ float Bs[BK][BN];

    const int block_m = blockIdx.y * BM;
    const int block_n = blockIdx.x * BN;
    const int tid  = threadIdx.x;
    const int trow = tid / 16;
    const int tcol = tid % 16;

    float acc[TM][TN], tot[TM][TN];
    #pragma unroll
    for (int i = 0; i < TM; i++)
        #pragma unroll
        for (int j = 0; j < TN; j++) { acc[i][j] = 0.f; tot[i][j] = 0.f; }

    for (int k0 = 0; k0 < D_IN; k0 += BK) {
        #pragma unroll
        for (int j = 0; j < 2; j++) {
            int idx = tid + j * 256;
            int row = idx >> 2;
            int k4  = (idx & 3) * 4;
            float4 v = *(const float4*)(X  + (size_t)(block_m + row) * D_IN + k0 + k4);
            As[k4 + 0][row] = v.x; As[k4 + 1][row] = v.y;
            As[k4 + 2][row] = v.z; As[k4 + 3][row] = v.w;
            float4 w = *(const float4*)(W1 + (size_t)(block_n + row) * D_IN + k0 + k4);
            Bs[k4 + 0][row] = w.x; Bs[k4 + 1][row] = w.y;
            Bs[k4 + 2][row] = w.z; Bs[k4 + 3][row] = w.w;
        }
        __syncthreads();

        #pragma unroll
        for (int k = 0; k < BK; k++) {
            float a[TM], b[TN];
            float4 a0 = *(const float4*)&As[k][trow * TM];
            float4 a1 = *(const float4*)&As[k][trow * TM + 4];
            a[0]=a0.x; a[1]=a0.y; a[2]=a0.z; a[3]=a0.w;
            a[4]=a1.x; a[5]=a1.y; a[6]=a1.z; a[7]=a1.w;
            float4 b0 = *(const float4*)&Bs[k][tcol * TN];
            float4 b1v= *(const float4*)&Bs[k][tcol * TN + 4];
            b[0]=b0.x; b[1]=b0.y; b[2]=b0.z; b[3]=b0.w;
            b[4]=b1v.x; b[5]=b1v.y; b[6]=b1v.z; b[7]=b1v.w;
            #pragma unroll
            for (int i = 0; i < TM; i++)
                #pragma unroll
                for (int j = 0; j < TN; j++)
                    acc[i][j] = fmaf(a[i], b[j], acc[i][j]);
        }
        __syncthreads();

        if (((k0 + BK) % KSPLIT1) == 0) {   // sequential panel fold
            #pragma unroll
            for (int i = 0; i < TM; i++)
                #pragma unroll
                for (int j = 0; j < TN; j++) {
                    tot[i][j] += acc[i][j];
                    acc[i][j] = 0.f;
                }
        }
    }

    #pragma unroll
    for (int i = 0; i < TM; i++) {
        int m = block_m + trow * TM + i;
        #pragma unroll
        for (int j4 = 0; j4 < TN; j4 += 4) {
            int n = block_n + tcol * TN + j4;
            float4 o;
            float v0 = tot[i][j4+0] + b1[n+0];
            float v1 = tot[i][j4+1] + b1[n+1];
            float v2 = tot[i][j4+2] + b1[n+2];
            float v3 = tot[i][j4+3] + b1[n+3];
            o.x = v0 >= 0.f ? v0 : SLOPE * v0;
            o.y = v1 >= 0.f ? v1 : SLOPE * v1;
            o.z = v2 >= 0.f ? v2 : SLOPE * v2;
            o.w = v3 >= 0.f ? v3 : SLOPE * v3;
            *(float4*)(g_H + (size_t)m * D_HID + n) = o;
        }
    }
}

// ---------------------------------------------------------------------------
// GEMM2: logits = H @ W2^T + b2.
// Ordering draw: 4 panels of 256 (ascending chains) combined as a PAIRWISE
// TREE: (p0+p1)+(p2+p3). Fused top-8 + softmax.
// 64 tokens x 64 experts per block, 256 threads.
// ---------------------------------------------------------------------------
#define K2CHUNK 32

__global__ __launch_bounds__(256)
void gemm2_topk_kernel(const float* __restrict__ W2,
                       const float* __restrict__ b2,
                       float* __restrict__ out,
                       int out_size)
{
    __shared__ float Hs[K2CHUNK][64];
    __shared__ float Ws[K2CHUNK][64];
    __shared__ float ls[64][N_EXP + 1];

    const int tok0 = blockIdx.x * 64;
    const int tid  = threadIdx.x;
    const int ttok = (tid / 16) * 4;
    const int texp = (tid % 16) * 4;

    float acc[4][4];        // current panel chain
    float pan[4][4][4];     // completed panels p0..p3
    #pragma unroll
    for (int i = 0; i < 4; i++)
        #pragma unroll
        for (int j = 0; j < 4; j++) {
            acc[i][j] = 0.f;
            #pragma unroll
            for (int p = 0; p < 4; p++) pan[p][i][j] = 0.f;
        }

    int panel = 0;
    for (int k0 = 0; k0 < D_HID; k0 += K2CHUNK) {
        #pragma unroll
        for (int j = 0; j < 2; j++) {
            int idx = tid + j * 256;
            int row = idx >> 3;
            int k4  = (idx & 7) * 4;
            float4 h = *(const float4*)(g_H + (size_t)(tok0 + row) * D_HID + k0 + k4);
            Hs[k4 + 0][row] = h.x; Hs[k4 + 1][row] = h.y;
            Hs[k4 + 2][row] = h.z; Hs[k4 + 3][row] = h.w;
            float4 w = *(const float4*)(W2 + (size_t)row * D_HID + k0 + k4);
            Ws[k4 + 0][row] = w.x; Ws[k4 + 1][row] = w.y;
            Ws[k4 + 2][row] = w.z; Ws[k4 + 3][row] = w.w;
        }
        __syncthreads();

        #pragma unroll
        for (int k = 0; k < K2CHUNK; k++) {
            float4 a = *(const float4*)&Hs[k][ttok];
            float4 b = *(const float4*)&Ws[k][texp];
            float av[4] = {a.x, a.y, a.z, a.w};
            float bv[4] = {b.x, b.y, b.z, b.w};
            #pragma unroll
            for (int i = 0; i < 4; i++)
                #pragma unroll
                for (int j = 0; j < 4; j++)
                    acc[i][j] = fmaf(av[i], bv[j], acc[i][j]);
        }
        __syncthreads();

        if (((k0 + K2CHUNK) % KSPLIT2) == 0) {   // stash panel, restart chain
            #pragma unroll
            for (int i = 0; i < 4; i++)
                #pragma unroll
                for (int j = 0; j < 4; j++) {
                    pan[panel][i][j] = acc[i][j];
                    acc[i][j] = 0.f;
                }
            panel++;
        }
    }

    // Pairwise-tree combine + bias
    #pragma unroll
    for (int i = 0; i < 4; i++)
        #pragma unroll
        for (int j = 0; j < 4; j++) {
            float lo = pan[0][i][j] + pan[1][i][j];
            float hi = pan[2][i][j] + pan[3][i][j];
            ls[ttok + i][texp + j] = (lo + hi) + b2[texp + j];
        }
    __syncthreads();

    // Top-8 + softmax, one thread per token. Strict '>' scan from index 0 ==
    // descending order, lowest-index tie-break (lax.top_k semantics).
    if (tid < 64) {
        const int t = tid;
        float vals[TOPK];
        int   idxs[TOPK];
        uint64_t taken = 0ull;
        #pragma unroll
        for (int j = 0; j < TOPK; j++) {
            float best = -3.4e38f;
            int bi = 0;
            for (int e = 0; e < N_EXP; e++) {
                bool free_ = !((taken >> e) & 1ull);
                float v = ls[t][e];
                if (free_ && v > best) { best = v; bi = e; }
            }
            taken |= (1ull << bi);
            vals[j] = best;
            idxs[j] = bi;
        }
        double m = (double)vals[0];
        double e8[TOPK];
        double s = 0.0;
        #pragma unroll
        for (int j = 0; j < TOPK; j++) { e8[j] = exp((double)vals[j] - m); s += e8[j]; }
        const int gt = tok0 + t;
        #pragma unroll
        for (int j = 0; j < TOPK; j++)
            out[(size_t)gt * TOPK + j] = (float)(e8[j] / s);
        if (out_size >= 2 * TOKENS * TOPK) {
            float* oid = out + (size_t)TOKENS * TOPK;
            #pragma unroll
            for (int j = 0; j < TOPK; j++)
                oid[(size_t)gt * TOPK + j] = (float)idxs[j];
        }
    }
}

// ---------------------------------------------------------------------------
extern "C" void kernel_launch(void* const* d_in, const int* in_sizes, int n_in,
                              void* d_out, int out_size)
{
    const float* X  = (const float*)d_in[0];
    const float* W1 = (const float*)d_in[1];
    const float* b1 = (const float*)d_in[2];
    const float* W2 = (const float*)d_in[3];
    const float* b2 = (const float*)d_in[4];
    float* out = (float*)d_out;

    dim3 g1(D_HID / BN, TOKENS / BM);   // (8, 128)
    gemm1_kernel<<<g1, 256>>>(X, W1, b1);

    gemm2_topk_kernel<<<TOKENS / 64, 256>>>(W2, b2, out, out_size);
}